// round 14
// baseline (speedup 1.0000x reference)
#include <cuda_runtime.h>
#include <cuda_bf16.h>
#include <cuda_fp16.h>
#include <math.h>
#include <stdint.h>

// ---------------------------------------------------------------------------
// Problem constants
// ---------------------------------------------------------------------------
#define BATCH     2
#define SEQ       4096
#define ROWS      (BATCH * SEQ)          // 8192 tokens
#define D_MODEL   1024
#define STATE     128
#define HEADDIM   64
#define D_INNER   2048
#define NHEADS    32
#define CONV_DIM  (D_INNER + 2 * STATE)  // 2304
#define D_IN_PROJ (2 * D_INNER + 2 * STATE + NHEADS) // 4384
#define N_INPROJ_PAD 4608                // padded to multiple of 256
#define MLP_INNER 4096
#define MLP_2X    (2 * MLP_INNER)        // interleaved gate/up
#define EPS       1e-5f
#define NCHUNK    32
#define CLEN      128                    // SEQ / NCHUNK

// ---------------------------------------------------------------------------
// Scratch (static device arrays; no runtime allocation allowed)
// ---------------------------------------------------------------------------
__device__ float g_res1  [(size_t)ROWS * D_MODEL];
__device__ float g_zx    [(size_t)ROWS * D_IN_PROJ];
__device__ float g_conv  [(size_t)ROWS * CONV_DIM];
__device__ float g_h2    [(size_t)ROWS * D_MODEL];

__device__ float g_slocal[(size_t)BATCH * NHEADS * NCHUNK * HEADDIM * STATE];
__device__ float g_sin   [(size_t)BATCH * NHEADS * NCHUNK * HEADDIM * STATE];
__device__ float g_cdec  [BATCH * NHEADS * NCHUNK];

__device__ __half g_norm [(size_t)ROWS * D_MODEL];
__device__ __half g_y    [(size_t)ROWS * D_INNER];
__device__ __half g_act  [(size_t)ROWS * MLP_INNER];

__device__ __half g_wi[(size_t)N_INPROJ_PAD * D_MODEL];
__device__ __half g_wo[(size_t)D_MODEL * D_INNER];
__device__ __half g_wm[(size_t)MLP_2X * D_MODEL];   // interleaved gate/up
__device__ __half g_wd[(size_t)D_MODEL * MLP_INNER];

// ---------------------------------------------------------------------------
// PTX helpers (baseline sm_103: cp.async + ldmatrix + mma.sync)
// ---------------------------------------------------------------------------
__device__ __forceinline__ uint32_t smem_u32(const void* p) {
    uint32_t a;
    asm("{ .reg .u64 t; cvta.to.shared.u64 t, %1; cvt.u32.u64 %0, t; }"
        : "=r"(a) : "l"(p));
    return a;
}
__device__ __forceinline__ void cp_async16(uint32_t dst, const void* src) {
    asm volatile("cp.async.cg.shared.global [%0], [%1], 16;\n" :: "r"(dst), "l"(src));
}
__device__ __forceinline__ void cp_commit() {
    asm volatile("cp.async.commit_group;\n" ::: "memory");
}
template <int N>
__device__ __forceinline__ void cp_wait() {
    asm volatile("cp.async.wait_group %0;\n" :: "n"(N) : "memory");
}
__device__ __forceinline__ void ldmx4(uint32_t* r, uint32_t addr) {
    asm volatile("ldmatrix.sync.aligned.m8n8.x4.shared.b16 {%0,%1,%2,%3}, [%4];"
                 : "=r"(r[0]), "=r"(r[1]), "=r"(r[2]), "=r"(r[3]) : "r"(addr));
}
__device__ __forceinline__ void mma_f16(float* c, const uint32_t* a, const uint32_t* b) {
    asm volatile(
        "mma.sync.aligned.m16n8k16.row.col.f32.f16.f16.f32 "
        "{%0,%1,%2,%3}, {%4,%5,%6,%7}, {%8,%9}, {%0,%1,%2,%3};"
        : "+f"(c[0]), "+f"(c[1]), "+f"(c[2]), "+f"(c[3])
        : "r"(a[0]), "r"(a[1]), "r"(a[2]), "r"(a[3]), "r"(b[0]), "r"(b[1]));
}
__device__ __forceinline__ float fast_silu(float x) {
    return __fdividef(x, 1.f + __expf(-x));
}

// ---------------------------------------------------------------------------
// fp16 tensor-core GEMM: C[M,N] = A[M,K] @ W[N,K]^T, fp32 accumulate.
// 128x256 CTA tile, BK=32, 512 threads (16 warps, 32x64 each), 4 stages.
// SMEM row stride 80B -> ldmatrix conflict-free without swizzle.
// SWIGLU=true: N covers interleaved (gate,up) pairs; epilogue emits
//   silu(gate)*up as fp16 into Out with N/2 columns.
// ---------------------------------------------------------------------------
#define GSTAGE   4
#define ROWB     80
#define A_TILE_B (128 * ROWB)            // 10240
#define W_TILE_B (256 * ROWB)            // 20480
#define STAGE_B  (A_TILE_B + W_TILE_B)   // 30720
#define GEMM_SMEM (GSTAGE * STAGE_B)     // 122880

__device__ __forceinline__ void load_stage_g(
    uint32_t sbase,
    const __half* __restrict__ A, const __half* __restrict__ W,
    int bm, int bn, int K, int kc, int tid)
{
    const int koff = kc * 32;
    {
        const int row = tid >> 2, ch = tid & 3;
        const uint32_t d = (uint32_t)(row * ROWB + ch * 16);
        cp_async16(sbase + d, A + (size_t)(bm + row) * K + koff + ch * 8);
    }
    #pragma unroll
    for (int i = 0; i < 2; i++) {
        const int slot = tid + i * 512;
        const int row = slot >> 2, ch = slot & 3;
        const uint32_t d = (uint32_t)(row * ROWB + ch * 16);
        cp_async16(sbase + A_TILE_B + d, W + (size_t)(bn + row) * K + koff + ch * 8);
    }
}

template <bool SWIGLU>
__global__ __launch_bounds__(512, 1)
void gemm_f16(const __half* __restrict__ A,
              const __half* __restrict__ W,
              float* __restrict__ C,
              __half* __restrict__ Out,
              int M, int N, int K)
{
    extern __shared__ __align__(128) char dynsmem[];
    const uint32_t sbase = smem_u32(dynsmem);

    const int tid  = threadIdx.x;
    const int lane = tid & 31;
    const int wid  = tid >> 5;
    const int wm   = wid & 3;             // 4 m-groups of 32 rows
    const int wn   = wid >> 2;            // 4 n-groups of 64 cols
    const int bm   = blockIdx.y * 128;
    const int bn   = blockIdx.x * 256;

    const uint32_t a_off = (uint32_t)((wm * 32 + (lane & 15)) * ROWB
                                      + ((lane >> 4) & 1) * 16);
    const uint32_t b_off = (uint32_t)((wn * 64 + ((lane >> 4) & 1) * 8 + (lane & 7)) * ROWB
                                      + ((lane >> 3) & 1) * 16);

    float acc[2][8][4];
    #pragma unroll
    for (int i = 0; i < 2; i++)
        #pragma unroll
        for (int j = 0; j < 8; j++)
            #pragma unroll
            for (int q = 0; q < 4; q++) acc[i][j][q] = 0.f;

    const int nk = K >> 5;

    load_stage_g(sbase + 0 * STAGE_B, A, W, bm, bn, K, 0, tid);
    cp_commit();
    load_stage_g(sbase + 1 * STAGE_B, A, W, bm, bn, K, 1, tid);
    cp_commit();
    load_stage_g(sbase + 2 * STAGE_B, A, W, bm, bn, K, 2, tid);
    cp_commit();

    for (int k = 0; k < nk; k++) {
        const uint32_t stb = sbase + (uint32_t)(k % GSTAGE) * STAGE_B;
        cp_wait<2>();
        __syncthreads();

        const int kn = k + 3;
        if (kn < nk)
            load_stage_g(sbase + (uint32_t)(kn % GSTAGE) * STAGE_B,
                         A, W, bm, bn, K, kn, tid);
        cp_commit();

        const uint32_t a_b = stb + a_off;
        const uint32_t b_b = stb + A_TILE_B + b_off;

        #pragma unroll
        for (int s = 0; s < 2; s++) {
            const uint32_t kb = (uint32_t)(s * 32);
            uint32_t af[2][4];
            #pragma unroll
            for (int i = 0; i < 2; i++)
                ldmx4(af[i], a_b + (uint32_t)(i * 16 * ROWB) + kb);
            #pragma unroll
            for (int jp = 0; jp < 4; jp++) {
                uint32_t wf[4];
                ldmx4(wf, b_b + (uint32_t)(jp * 16 * ROWB) + kb);
                #pragma unroll
                for (int i = 0; i < 2; i++)
                    #pragma unroll
                    for (int f = 0; f < 2; f++)
                        mma_f16(acc[i][jp * 2 + f], af[i], wf + f * 2);
            }
        }
    }

    if (!SWIGLU) {
        #pragma unroll
        for (int i = 0; i < 2; i++) {
            const int row = bm + wm * 32 + i * 16 + (lane >> 2);
            #pragma unroll
            for (int j = 0; j < 8; j++) {
                const int col = bn + wn * 64 + j * 8 + (lane & 3) * 2;
                if (col < N) {
                    *(float2*)&C[(size_t)row * N + col] =
                        make_float2(acc[i][j][0], acc[i][j][1]);
                    *(float2*)&C[(size_t)(row + 8) * N + col] =
                        make_float2(acc[i][j][2], acc[i][j][3]);
                }
            }
        }
    } else {
        // Columns are interleaved (gate, up) pairs: acc[..][0]=gate, [1]=up
        // (and [2],[3] for row+8). Output column index = col/2, width N/2.
        const int NO = N >> 1;
        #pragma unroll
        for (int i = 0; i < 2; i++) {
            const int row = bm + wm * 32 + i * 16 + (lane >> 2);
            #pragma unroll
            for (int j = 0; j < 8; j++) {
                const int colc = (bn + wn * 64 + j * 8 + (lane & 3) * 2) >> 1;
                {
                    const float v = fast_silu(acc[i][j][0]) * acc[i][j][1];
                    Out[(size_t)row * NO + colc] = __float2half(v);
                }
                {
                    const float v = fast_silu(acc[i][j][2]) * acc[i][j][3];
                    Out[(size_t)(row + 8) * NO + colc] = __float2half(v);
                }
            }
        }
    }
}

// ---------------------------------------------------------------------------
// fp16 helpers
// ---------------------------------------------------------------------------
__device__ __forceinline__ void store_h4(__half* __restrict__ p, size_t off, float4 v) {
    __half2 a; a.x = __float2half(v.x); a.y = __float2half(v.y);
    __half2 b; b.x = __float2half(v.z); b.y = __float2half(v.w);
    *(__half2*)(p + off)     = a;
    *(__half2*)(p + off + 2) = b;
}

// Weight fp32 -> fp16, float4-vectorized, zero tail padding.
__global__ __launch_bounds__(256) void cvt_weight_kernel(
    const float* __restrict__ w, __half* __restrict__ out,
    size_t n_real4, size_t n_total4)
{
    const size_t i = (size_t)blockIdx.x * 256 + threadIdx.x;
    if (i >= n_total4) return;
    float4 v = (i < n_real4) ? ((const float4*)w)[i]
                             : make_float4(0.f, 0.f, 0.f, 0.f);
    store_h4(out, i * 4, v);
}

// gate/up weights -> row-interleaved fp16: row 2j = gate_j, 2j+1 = up_j.
#define K4 (D_MODEL / 4)
__global__ __launch_bounds__(256) void cvt_weight_pair_kernel(
    const float* __restrict__ wg, const float* __restrict__ wu,
    __half* __restrict__ out)
{
    const size_t i = (size_t)blockIdx.x * 256 + threadIdx.x;   // float4 index
    if (i >= (size_t)MLP_2X * K4) return;
    const size_t n = i / K4;          // interleaved row
    const size_t k4 = i % K4;
    const size_t srow = n >> 1;
    const float4 v = (n & 1) ? ((const float4*)wu)[srow * K4 + k4]
                             : ((const float4*)wg)[srow * K4 + k4];
    store_h4(out, i * 4, v);
}

// ---------------------------------------------------------------------------
// Fused residual-add + RMSNorm; norm output as fp16.
// ---------------------------------------------------------------------------
__global__ __launch_bounds__(256) void rmsnorm_prenorm_kernel(
    const float* __restrict__ x, const float* __restrict__ res_in,
    const float* __restrict__ w, float* __restrict__ res_out,
    __half* __restrict__ nh)
{
    const size_t row = blockIdx.x;
    const int tid = threadIdx.x;
    const float4 xv = ((const float4*)(x      + row * D_MODEL))[tid];
    const float4 rv = ((const float4*)(res_in + row * D_MODEL))[tid];
    float4 s;
    s.x = xv.x + rv.x; s.y = xv.y + rv.y; s.z = xv.z + rv.z; s.w = xv.w + rv.w;
    float ss = s.x * s.x + s.y * s.y + s.z * s.z + s.w * s.w;

    #pragma unroll
    for (int o = 16; o > 0; o >>= 1) ss += __shfl_down_sync(0xffffffffu, ss, o);
    __shared__ float red[8];
    __shared__ float scale_sh;
    if ((tid & 31) == 0) red[tid >> 5] = ss;
    __syncthreads();
    if (tid == 0) {
        float t = 0.f;
        #pragma unroll
        for (int i = 0; i < 8; i++) t += red[i];
        scale_sh = rsqrtf(t / (float)D_MODEL + EPS);
    }
    __syncthreads();
    const float scale = scale_sh;

    ((float4*)(res_out + row * D_MODEL))[tid] = s;
    const float4 wv = ((const float4*)w)[tid];
    float4 o;
    o.x = s.x * scale * wv.x; o.y = s.y * scale * wv.y;
    o.z = s.z * scale * wv.z; o.w = s.w * scale * wv.w;
    store_h4(nh, row * D_MODEL + (size_t)tid * 4, o);
}

// ---------------------------------------------------------------------------
// Causal depthwise conv1d (width 4) + SiLU over the xBC slice of zxbcdt.
// ---------------------------------------------------------------------------
__global__ __launch_bounds__(256) void conv_silu_kernel(
    const float* __restrict__ zx, const float* __restrict__ cw,
    const float* __restrict__ cb, float* __restrict__ out)
{
    const size_t id = (size_t)blockIdx.x * 256 + threadIdx.x;
    if (id >= (size_t)ROWS * CONV_DIM) return;
    const int c = (int)(id % CONV_DIM);
    const size_t r = id / CONV_DIM;
    const int l = (int)(r & (SEQ - 1));
    const float* base = zx + r * D_IN_PROJ + D_INNER + c;

    const float w0 = cw[c * 4 + 0], w1 = cw[c * 4 + 1];
    const float w2 = cw[c * 4 + 2], w3 = cw[c * 4 + 3];
    float acc = cb[c];
    if (l >= 3) acc += base[-3L * D_IN_PROJ] * w0;
    if (l >= 2) acc += base[-2L * D_IN_PROJ] * w1;
    if (l >= 1) acc += base[-1L * D_IN_PROJ] * w2;
    acc += base[0] * w3;
    out[id] = fast_silu(acc);
}

// ---------------------------------------------------------------------------
// Chunked selective scan with decay-rescaled recurrence.
// Within each 8-step window with local decay prefix Q_t:
//   R += (dtp_t / Q_t) * x[p] * B_t[n]      (scale folded into B smem tile)
//   y_t = (Q_t * C_t) . R                   (scale folded into C smem tile)
//   window end: R *= Q_end
// Log-prefix clamped at -60 to keep 1/Q finite (affected weights ~e-60 ~ 0).
// Phase 1: per-chunk local scan (R starts 0), writes final state + decay.
// ---------------------------------------------------------------------------
#define SCAN_T 8
__global__ __launch_bounds__(128) void scan_local_kernel(
    const float* __restrict__ conv, const float* __restrict__ zx,
    const float* __restrict__ dt_bias, const float* __restrict__ A_log)
{
    const int chunk = blockIdx.x;
    const int bh = blockIdx.y;
    const int b = bh >> 5;
    const int h = bh & 31;
    const int tid = threadIdx.x;
    const int p = tid >> 1;
    const int half = tid & 1;
    const int n0 = half * 64;

    __shared__ float Bs[SCAN_T][STATE];
    __shared__ float xs[SCAN_T][HEADDIM];
    __shared__ float lqs[CLEN];
    __shared__ float bsc_s[CLEN];
    __shared__ float csc_s[CLEN];

    float state[64];
    #pragma unroll
    for (int j = 0; j < 64; j++) state[j] = 0.f;

    const float Aneg = -__expf(A_log[h]);
    const float dtb  = dt_bias[h];
    const size_t base_conv = (size_t)b * SEQ * CONV_DIM;
    const size_t base_z    = (size_t)b * SEQ * D_IN_PROJ;
    const int tstart = chunk * CLEN;

    // Pre-compute per-timestep dtp and window-local decay prefixes (once).
    float my_dtp;
    {
        const float draw = zx[base_z + (size_t)(tstart + tid) * D_IN_PROJ
                              + D_INNER + CONV_DIM + h] + dtb;
        my_dtp = (draw > 20.f) ? draw : log1pf(__expf(draw));
        lqs[tid] = my_dtp * Aneg;
    }
    __syncthreads();
    {
        const int w0 = tid & ~(SCAN_T - 1);
        float s = 0.f;
        for (int u = w0; u <= tid; u++) s += lqs[u];
        s = fmaxf(s, -60.f);
        csc_s[tid] = __expf(s);
        bsc_s[tid] = my_dtp * __expf(-s);
    }
    if (tid == 0) {
        float s = 0.f;
        #pragma unroll
        for (int u = 0; u < CLEN; u++) s += lqs[u];
        g_cdec[bh * NCHUNK + chunk] = __expf(s);
    }

    for (int lt = 0; lt < CLEN; lt += SCAN_T) {
        __syncthreads();
        for (int idx = tid; idx < SCAN_T * STATE; idx += 128) {
            const int tt = idx >> 7;
            const int n  = idx & 127;
            Bs[tt][n] = conv[base_conv + (size_t)(tstart + lt + tt) * CONV_DIM
                             + D_INNER + n] * bsc_s[lt + tt];
        }
        for (int idx = tid; idx < SCAN_T * HEADDIM; idx += 128) {
            const int tt = idx >> 6;
            const int pp = idx & 63;
            xs[tt][pp] = conv[base_conv + (size_t)(tstart + lt + tt) * CONV_DIM
                              + h * HEADDIM + pp];
        }
        __syncthreads();

        #pragma unroll 1
        for (int tt = 0; tt < SCAN_T; tt++) {
            const float xv = xs[tt][p];
            const float4* Bv = (const float4*)&Bs[tt][n0];
            #pragma unroll
            for (int jj = 0; jj < 16; jj++) {
                const float4 bv = Bv[jj];
                float* st = &state[jj * 4];
                st[0] += xv * bv.x;
                st[1] += xv * bv.y;
                st[2] += xv * bv.z;
                st[3] += xv * bv.w;
            }
        }
        const float Qe = csc_s[lt + SCAN_T - 1];
        #pragma unroll
        for (int j = 0; j < 64; j++) state[j] *= Qe;
    }

    float* dst = g_slocal + ((size_t)(bh * NCHUNK + chunk) * HEADDIM + p) * STATE + n0;
    #pragma unroll
    for (int jj = 0; jj < 16; jj++)
        ((float4*)dst)[jj] = make_float4(state[jj * 4], state[jj * 4 + 1],
                                         state[jj * 4 + 2], state[jj * 4 + 3]);
}

// Phase 2: sequential chunk combine (scalar decay per chunk).
// Grid: (B*H, 8 slices) = 512 CTAs; each thread carries 4 elements.
__global__ __launch_bounds__(256) void scan_combine_kernel()
{
    const int bh = blockIdx.x;
    const int slice = blockIdx.y;                 // 0..7
    const int tid = threadIdx.x;
    const int e0 = slice * 1024 + tid;            // element base; +256*j
    float s[4];
    #pragma unroll
    for (int j = 0; j < 4; j++) s[j] = 0.f;

    for (int c = 0; c < NCHUNK; c++) {
        float* dst = g_sin + (size_t)(bh * NCHUNK + c) * (HEADDIM * STATE);
        if (c > 0) {
            const float D = g_cdec[bh * NCHUNK + c - 1];
            const float* src = g_slocal + (size_t)(bh * NCHUNK + c - 1) * (HEADDIM * STATE);
            #pragma unroll
            for (int j = 0; j < 4; j++)
                s[j] = D * s[j] + src[e0 + j * 256];
        }
        #pragma unroll
        for (int j = 0; j < 4; j++)
            dst[e0 + j * 256] = s[j];
    }
}

// Phase 3: per-chunk scan (rescaled recurrence) with initial state; gated fp16 y.
__global__ __launch_bounds__(128) void scan_apply_kernel(
    const float* __restrict__ conv, const float* __restrict__ zx,
    const float* __restrict__ dt_bias, const float* __restrict__ A_log,
    const float* __restrict__ D_param,
    __half* __restrict__ yh)
{
    const int chunk = blockIdx.x;
    const int bh = blockIdx.y;
    const int b = bh >> 5;
    const int h = bh & 31;
    const int tid = threadIdx.x;
    const int p = tid >> 1;
    const int half = tid & 1;
    const int n0 = half * 64;

    __shared__ float Bs[SCAN_T][STATE];
    __shared__ float Cs[SCAN_T][STATE];
    __shared__ float xs[SCAN_T][HEADDIM];
    __shared__ float zs[SCAN_T][HEADDIM];
    __shared__ float lqs[CLEN];
    __shared__ float bsc_s[CLEN];
    __shared__ float csc_s[CLEN];

    float state[64];
    {
        const float* src = g_sin + ((size_t)(bh * NCHUNK + chunk) * HEADDIM + p) * STATE + n0;
        #pragma unroll
        for (int jj = 0; jj < 16; jj++) {
            const float4 v = ((const float4*)src)[jj];
            state[jj * 4] = v.x; state[jj * 4 + 1] = v.y;
            state[jj * 4 + 2] = v.z; state[jj * 4 + 3] = v.w;
        }
    }

    const float Aneg = -__expf(A_log[h]);
    const float dtb  = dt_bias[h];
    const float Dp   = D_param[h];
    const size_t base_conv = (size_t)b * SEQ * CONV_DIM;
    const size_t base_z    = (size_t)b * SEQ * D_IN_PROJ;
    const int tstart = chunk * CLEN;

    // Pre-compute per-timestep dtp and window-local decay prefixes (once).
    float my_dtp;
    {
        const float draw = zx[base_z + (size_t)(tstart + tid) * D_IN_PROJ
                              + D_INNER + CONV_DIM + h] + dtb;
        my_dtp = (draw > 20.f) ? draw : log1pf(__expf(draw));
        lqs[tid] = my_dtp * Aneg;
    }
    __syncthreads();
    {
        const int w0 = tid & ~(SCAN_T - 1);
        float s = 0.f;
        for (int u = w0; u <= tid; u++) s += lqs[u];
        s = fmaxf(s, -60.f);
        csc_s[tid] = __expf(s);
        bsc_s[tid] = my_dtp * __expf(-s);
    }

    for (int lt = 0; lt < CLEN; lt += SCAN_T) {
        __syncthreads();
        for (int idx = tid; idx < SCAN_T * STATE; idx += 128) {
            const int tt = idx >> 7;
            const int n  = idx & 127;
            const size_t rowp = base_conv + (size_t)(tstart + lt + tt) * CONV_DIM;
            Bs[tt][n] = conv[rowp + D_INNER + n] * bsc_s[lt + tt];
            Cs[tt][n] = conv[rowp + D_INNER + STATE + n] * csc_s[lt + tt];
        }
        for (int idx = tid; idx < SCAN_T * HEADDIM; idx += 128) {
            const int tt = idx >> 6;
            const int pp = idx & 63;
            const size_t tg = (size_t)(tstart + lt + tt);
            xs[tt][pp] = conv[base_conv + tg * CONV_DIM + h * HEADDIM + pp];
            zs[tt][pp] = zx[base_z + tg * D_IN_PROJ + h * HEADDIM + pp];
        }
        __syncthreads();

        #pragma unroll 1
        for (int tt = 0; tt < SCAN_T; tt++) {
            const float xv = xs[tt][p];
            float y0 = 0.f, y1 = 0.f, y2 = 0.f, y3 = 0.f;
            const float4* Bv = (const float4*)&Bs[tt][n0];
            const float4* Cv = (const float4*)&Cs[tt][n0];
            #pragma unroll
            for (int jj = 0; jj < 16; jj++) {
                const float4 bv = Bv[jj];
                const float4 cv = Cv[jj];
                float* st = &state[jj * 4];
                st[0] += xv * bv.x; y0 += st[0] * cv.x;
                st[1] += xv * bv.y; y1 += st[1] * cv.y;
                st[2] += xv * bv.z; y2 += st[2] * cv.z;
                st[3] += xv * bv.w; y3 += st[3] * cv.w;
            }
            float y = (y0 + y1) + (y2 + y3);
            y += __shfl_xor_sync(0xffffffffu, y, 1);
            if (half == 0) {
                const float gate = fast_silu(zs[tt][p]);
                const float yo = (y + Dp * xv) * gate;
                yh[((size_t)(b * SEQ + tstart + lt + tt)) * D_INNER + h * HEADDIM + p] =
                    __float2half(yo);
            }
        }
        const float Qe = csc_s[lt + SCAN_T - 1];
        #pragma unroll
        for (int j = 0; j < 64; j++) state[j] *= Qe;
    }
}

// ---------------------------------------------------------------------------
// Launch
// ---------------------------------------------------------------------------
extern "C" void kernel_launch(void* const* d_in, const int* in_sizes, int n_in,
                              void* d_out, int out_size)
{
    const float* hidden     = (const float*)d_in[0];
    const float* residual   = (const float*)d_in[1];
    const float* ssm_norm_w = (const float*)d_in[2];
    const float* mlp_norm_w = (const float*)d_in[3];
    const float* in_proj_w  = (const float*)d_in[4];
    const float* conv_w     = (const float*)d_in[5];
    const float* conv_b     = (const float*)d_in[6];
    const float* dt_bias    = (const float*)d_in[7];
    const float* A_log      = (const float*)d_in[8];
    const float* D_param    = (const float*)d_in[9];
    const float* out_proj_w = (const float*)d_in[10];
    const float* mlp_gate_w = (const float*)d_in[11];
    const float* mlp_up_w   = (const float*)d_in[12];
    const float* mlp_down_w = (const float*)d_in[13];

    float* out_h   = (float*)d_out;
    float* out_res = out_h + (size_t)ROWS * D_MODEL;

    void *p_res1, *p_zx, *p_conv, *p_h2;
    void *p_n, *p_y, *p_a;
    void *p_wi, *p_wo, *p_wm, *p_wd;
    cudaGetSymbolAddress(&p_res1, g_res1);
    cudaGetSymbolAddress(&p_zx,   g_zx);
    cudaGetSymbolAddress(&p_conv, g_conv);
    cudaGetSymbolAddress(&p_h2,   g_h2);
    cudaGetSymbolAddress(&p_n,    g_norm);
    cudaGetSymbolAddress(&p_y,    g_y);
    cudaGetSymbolAddress(&p_a,    g_act);
    cudaGetSymbolAddress(&p_wi,   g_wi);
    cudaGetSymbolAddress(&p_wo,   g_wo);
    cudaGetSymbolAddress(&p_wm,   g_wm);
    cudaGetSymbolAddress(&p_wd,   g_wd);

    cudaFuncSetAttribute(gemm_f16<false>,
                         cudaFuncAttributeMaxDynamicSharedMemorySize, GEMM_SMEM);
    cudaFuncSetAttribute(gemm_f16<true>,
                         cudaFuncAttributeMaxDynamicSharedMemorySize, GEMM_SMEM);

    // Weight conversions (fp16, padding / interleave)
    {
        size_t nr, nt;
        nr = (size_t)D_IN_PROJ * D_MODEL / 4; nt = (size_t)N_INPROJ_PAD * D_MODEL / 4;
        cvt_weight_kernel<<<(unsigned)((nt + 255) / 256), 256>>>(
            in_proj_w, (__half*)p_wi, nr, nt);
        nr = nt = (size_t)D_MODEL * D_INNER / 4;
        cvt_weight_kernel<<<(unsigned)((nt + 255) / 256), 256>>>(
            out_proj_w, (__half*)p_wo, nr, nt);
        nt = (size_t)MLP_2X * D_MODEL / 4;
        cvt_weight_pair_kernel<<<(unsigned)((nt + 255) / 256), 256>>>(
            mlp_gate_w, mlp_up_w, (__half*)p_wm);
        nr = nt = (size_t)D_MODEL * MLP_INNER / 4;
        cvt_weight_kernel<<<(unsigned)((nt + 255) / 256), 256>>>(
            mlp_down_w, (__half*)p_wd, nr, nt);
    }

    // 1) prenorm RMSNorm #1
    rmsnorm_prenorm_kernel<<<ROWS, 256>>>(hidden, residual, ssm_norm_w,
        (float*)p_res1, (__half*)p_n);
    // 2) in_proj
    gemm_f16<false><<<dim3(N_INPROJ_PAD / 256, ROWS / 128), 512, GEMM_SMEM>>>(
        (const __half*)p_n, (const __half*)p_wi,
        (float*)p_zx, nullptr, ROWS, D_IN_PROJ, D_MODEL);
    // 3) causal depthwise conv + SiLU
    conv_silu_kernel<<<(unsigned)(((size_t)ROWS * CONV_DIM + 255) / 256), 256>>>(
        (const float*)p_zx, conv_w, conv_b, (float*)p_conv);
    // 4) chunked selective scan (3 phases)
    scan_local_kernel<<<dim3(NCHUNK, BATCH * NHEADS), 128>>>(
        (const float*)p_conv, (const float*)p_zx, dt_bias, A_log);
    scan_combine_kernel<<<dim3(BATCH * NHEADS, 8), 256>>>();
    scan_apply_kernel<<<dim3(NCHUNK, BATCH * NHEADS), 128>>>(
        (const float*)p_conv, (const float*)p_zx, dt_bias, A_log, D_param,
        (__half*)p_y);
    // 5) out_proj
    gemm_f16<false><<<dim3(D_MODEL / 256, ROWS / 128), 512, GEMM_SMEM>>>(
        (const __half*)p_y, (const __half*)p_wo,
        (float*)p_h2, nullptr, ROWS, D_MODEL, D_INNER);
    // 6) prenorm RMSNorm #2
    rmsnorm_prenorm_kernel<<<ROWS, 256>>>((const float*)p_h2, (const float*)p_res1,
        mlp_norm_w, out_res, (__half*)p_n);
    // 7) fused MLP gate+up GEMM with SwiGLU epilogue (interleaved weights)
    gemm_f16<true><<<dim3(MLP_2X / 256, ROWS / 128), 512, GEMM_SMEM>>>(
        (const __half*)p_n, (const __half*)p_wm,
        nullptr, (__half*)p_a, ROWS, MLP_2X, D_MODEL);
    // 8) down projection -> first model output
    gemm_f16<false><<<dim3(D_MODEL / 256, ROWS / 128), 512, GEMM_SMEM>>>(
        (const __half*)p_a, (const __half*)p_wd,
        out_h, nullptr, ROWS, D_MODEL, MLP_INNER);
}

// round 15
// speedup vs baseline: 1.0619x; 1.0619x over previous
#include <cuda_runtime.h>
#include <cuda_bf16.h>
#include <cuda_fp16.h>
#include <math.h>
#include <stdint.h>

// ---------------------------------------------------------------------------
// Problem constants
// ---------------------------------------------------------------------------
#define BATCH     2
#define SEQ       4096
#define ROWS      (BATCH * SEQ)          // 8192 tokens
#define D_MODEL   1024
#define STATE     128
#define HEADDIM   64
#define D_INNER   2048
#define NHEADS    32
#define CONV_DIM  (D_INNER + 2 * STATE)  // 2304
#define D_IN_PROJ (2 * D_INNER + 2 * STATE + NHEADS) // 4384
#define ZX16_W    (D_INNER + CONV_DIM)   // 4352 fp16 cols (z + xBC)
#define N_INPROJ_PAD 4608                // padded to multiple of 256
#define MLP_INNER 4096
#define MLP_2X    (2 * MLP_INNER)        // interleaved gate/up
#define EPS       1e-5f
#define NCHUNK    32
#define CLEN      128                    // SEQ / NCHUNK

// ---------------------------------------------------------------------------
// Scratch (static device arrays; no runtime allocation allowed)
// ---------------------------------------------------------------------------
__device__ float g_res1  [(size_t)ROWS * D_MODEL];
__device__ float g_h2    [(size_t)ROWS * D_MODEL];
__device__ float g_dt    [(size_t)ROWS * NHEADS];          // fp32 dt (precision)

__device__ float g_slocal[(size_t)BATCH * NHEADS * NCHUNK * HEADDIM * STATE];
__device__ float g_sin   [(size_t)BATCH * NHEADS * NCHUNK * HEADDIM * STATE];
__device__ float g_cdec  [BATCH * NHEADS * NCHUNK];

__device__ __half g_zx16 [(size_t)ROWS * ZX16_W];          // z + xBC, fp16
__device__ __half g_cv16 [(size_t)ROWS * CONV_DIM];        // conv output, fp16
__device__ __half g_norm [(size_t)ROWS * D_MODEL];
__device__ __half g_y    [(size_t)ROWS * D_INNER];
__device__ __half g_act  [(size_t)ROWS * MLP_INNER];

__device__ __half g_wi[(size_t)N_INPROJ_PAD * D_MODEL];
__device__ __half g_wo[(size_t)D_MODEL * D_INNER];
__device__ __half g_wm[(size_t)MLP_2X * D_MODEL];   // interleaved gate/up
__device__ __half g_wd[(size_t)D_MODEL * MLP_INNER];

// ---------------------------------------------------------------------------
// PTX helpers (baseline sm_103: cp.async + ldmatrix + mma.sync)
// ---------------------------------------------------------------------------
__device__ __forceinline__ uint32_t smem_u32(const void* p) {
    uint32_t a;
    asm("{ .reg .u64 t; cvta.to.shared.u64 t, %1; cvt.u32.u64 %0, t; }"
        : "=r"(a) : "l"(p));
    return a;
}
__device__ __forceinline__ void cp_async16(uint32_t dst, const void* src) {
    asm volatile("cp.async.cg.shared.global [%0], [%1], 16;\n" :: "r"(dst), "l"(src));
}
__device__ __forceinline__ void cp_commit() {
    asm volatile("cp.async.commit_group;\n" ::: "memory");
}
template <int N>
__device__ __forceinline__ void cp_wait() {
    asm volatile("cp.async.wait_group %0;\n" :: "n"(N) : "memory");
}
__device__ __forceinline__ void ldmx4(uint32_t* r, uint32_t addr) {
    asm volatile("ldmatrix.sync.aligned.m8n8.x4.shared.b16 {%0,%1,%2,%3}, [%4];"
                 : "=r"(r[0]), "=r"(r[1]), "=r"(r[2]), "=r"(r[3]) : "r"(addr));
}
__device__ __forceinline__ void mma_f16(float* c, const uint32_t* a, const uint32_t* b) {
    asm volatile(
        "mma.sync.aligned.m16n8k16.row.col.f32.f16.f16.f32 "
        "{%0,%1,%2,%3}, {%4,%5,%6,%7}, {%8,%9}, {%0,%1,%2,%3};"
        : "+f"(c[0]), "+f"(c[1]), "+f"(c[2]), "+f"(c[3])
        : "r"(a[0]), "r"(a[1]), "r"(a[2]), "r"(a[3]), "r"(b[0]), "r"(b[1]));
}
__device__ __forceinline__ float fast_silu(float x) {
    return __fdividef(x, 1.f + __expf(-x));
}

// ---------------------------------------------------------------------------
// fp16 tensor-core GEMM: C[M,N] = A[M,K] @ W[N,K]^T, fp32 accumulate.
// 128x256 CTA tile, BK=32, 512 threads (16 warps, 32x64 each), 4 stages.
// MODE 0: fp32 C.  MODE 1: SwiGLU epilogue (interleaved gate/up -> fp16 Out).
// MODE 2: in_proj split epilogue: cols<ZX16_W -> fp16 OutH (width ZX16_W),
//         cols in [ZX16_W, D_IN_PROJ) -> fp32 dt buffer (width NHEADS).
// ---------------------------------------------------------------------------
#define GSTAGE   4
#define ROWB     80
#define A_TILE_B (128 * ROWB)            // 10240
#define W_TILE_B (256 * ROWB)            // 20480
#define STAGE_B  (A_TILE_B + W_TILE_B)   // 30720
#define GEMM_SMEM (GSTAGE * STAGE_B)     // 122880

__device__ __forceinline__ void load_stage_g(
    uint32_t sbase,
    const __half* __restrict__ A, const __half* __restrict__ W,
    int bm, int bn, int K, int kc, int tid)
{
    const int koff = kc * 32;
    {
        const int row = tid >> 2, ch = tid & 3;
        const uint32_t d = (uint32_t)(row * ROWB + ch * 16);
        cp_async16(sbase + d, A + (size_t)(bm + row) * K + koff + ch * 8);
    }
    #pragma unroll
    for (int i = 0; i < 2; i++) {
        const int slot = tid + i * 512;
        const int row = slot >> 2, ch = slot & 3;
        const uint32_t d = (uint32_t)(row * ROWB + ch * 16);
        cp_async16(sbase + A_TILE_B + d, W + (size_t)(bn + row) * K + koff + ch * 8);
    }
}

template <int MODE>
__global__ __launch_bounds__(512, 1)
void gemm_f16(const __half* __restrict__ A,
              const __half* __restrict__ W,
              float* __restrict__ C,
              __half* __restrict__ Out,
              float* __restrict__ Dt,
              int M, int N, int K)
{
    extern __shared__ __align__(128) char dynsmem[];
    const uint32_t sbase = smem_u32(dynsmem);

    const int tid  = threadIdx.x;
    const int lane = tid & 31;
    const int wid  = tid >> 5;
    const int wm   = wid & 3;             // 4 m-groups of 32 rows
    const int wn   = wid >> 2;            // 4 n-groups of 64 cols
    const int bm   = blockIdx.y * 128;
    const int bn   = blockIdx.x * 256;

    const uint32_t a_off = (uint32_t)((wm * 32 + (lane & 15)) * ROWB
                                      + ((lane >> 4) & 1) * 16);
    const uint32_t b_off = (uint32_t)((wn * 64 + ((lane >> 4) & 1) * 8 + (lane & 7)) * ROWB
                                      + ((lane >> 3) & 1) * 16);

    float acc[2][8][4];
    #pragma unroll
    for (int i = 0; i < 2; i++)
        #pragma unroll
        for (int j = 0; j < 8; j++)
            #pragma unroll
            for (int q = 0; q < 4; q++) acc[i][j][q] = 0.f;

    const int nk = K >> 5;

    load_stage_g(sbase + 0 * STAGE_B, A, W, bm, bn, K, 0, tid);
    cp_commit();
    load_stage_g(sbase + 1 * STAGE_B, A, W, bm, bn, K, 1, tid);
    cp_commit();
    load_stage_g(sbase + 2 * STAGE_B, A, W, bm, bn, K, 2, tid);
    cp_commit();

    for (int k = 0; k < nk; k++) {
        const uint32_t stb = sbase + (uint32_t)(k % GSTAGE) * STAGE_B;
        cp_wait<2>();
        __syncthreads();

        const int kn = k + 3;
        if (kn < nk)
            load_stage_g(sbase + (uint32_t)(kn % GSTAGE) * STAGE_B,
                         A, W, bm, bn, K, kn, tid);
        cp_commit();

        const uint32_t a_b = stb + a_off;
        const uint32_t b_b = stb + A_TILE_B + b_off;

        #pragma unroll
        for (int s = 0; s < 2; s++) {
            const uint32_t kb = (uint32_t)(s * 32);
            uint32_t af[2][4];
            #pragma unroll
            for (int i = 0; i < 2; i++)
                ldmx4(af[i], a_b + (uint32_t)(i * 16 * ROWB) + kb);
            #pragma unroll
            for (int jp = 0; jp < 4; jp++) {
                uint32_t wf[4];
                ldmx4(wf, b_b + (uint32_t)(jp * 16 * ROWB) + kb);
                #pragma unroll
                for (int i = 0; i < 2; i++)
                    #pragma unroll
                    for (int f = 0; f < 2; f++)
                        mma_f16(acc[i][jp * 2 + f], af[i], wf + f * 2);
            }
        }
    }

    #pragma unroll
    for (int i = 0; i < 2; i++) {
        const int row0 = bm + wm * 32 + i * 16 + (lane >> 2);
        #pragma unroll
        for (int j = 0; j < 8; j++) {
            const int col = bn + wn * 64 + j * 8 + (lane & 3) * 2;
            if (MODE == 0) {
                if (col < N) {
                    *(float2*)&C[(size_t)row0 * N + col] =
                        make_float2(acc[i][j][0], acc[i][j][1]);
                    *(float2*)&C[(size_t)(row0 + 8) * N + col] =
                        make_float2(acc[i][j][2], acc[i][j][3]);
                }
            } else if (MODE == 1) {
                const int NO = N >> 1;
                const int colc = col >> 1;
                {
                    const float v = fast_silu(acc[i][j][0]) * acc[i][j][1];
                    Out[(size_t)row0 * NO + colc] = __float2half(v);
                }
                {
                    const float v = fast_silu(acc[i][j][2]) * acc[i][j][3];
                    Out[(size_t)(row0 + 8) * NO + colc] = __float2half(v);
                }
            } else {  // MODE 2: in_proj split
                if (col < ZX16_W) {
                    __half2 v0; v0.x = __float2half(acc[i][j][0]);
                                v0.y = __float2half(acc[i][j][1]);
                    __half2 v1; v1.x = __float2half(acc[i][j][2]);
                                v1.y = __float2half(acc[i][j][3]);
                    *(__half2*)&Out[(size_t)row0 * ZX16_W + col]       = v0;
                    *(__half2*)&Out[(size_t)(row0 + 8) * ZX16_W + col] = v1;
                } else if (col < D_IN_PROJ) {
                    const int dc = col - ZX16_W;
                    *(float2*)&Dt[(size_t)row0 * NHEADS + dc] =
                        make_float2(acc[i][j][0], acc[i][j][1]);
                    *(float2*)&Dt[(size_t)(row0 + 8) * NHEADS + dc] =
                        make_float2(acc[i][j][2], acc[i][j][3]);
                }
            }
        }
    }
}

// ---------------------------------------------------------------------------
// fp16 helpers
// ---------------------------------------------------------------------------
__device__ __forceinline__ void store_h4(__half* __restrict__ p, size_t off, float4 v) {
    __half2 a; a.x = __float2half(v.x); a.y = __float2half(v.y);
    __half2 b; b.x = __float2half(v.z); b.y = __float2half(v.w);
    *(__half2*)(p + off)     = a;
    *(__half2*)(p + off + 2) = b;
}

// Weight fp32 -> fp16, float4-vectorized, zero tail padding.
__global__ __launch_bounds__(256) void cvt_weight_kernel(
    const float* __restrict__ w, __half* __restrict__ out,
    size_t n_real4, size_t n_total4)
{
    const size_t i = (size_t)blockIdx.x * 256 + threadIdx.x;
    if (i >= n_total4) return;
    float4 v = (i < n_real4) ? ((const float4*)w)[i]
                             : make_float4(0.f, 0.f, 0.f, 0.f);
    store_h4(out, i * 4, v);
}

// gate/up weights -> row-interleaved fp16: row 2j = gate_j, 2j+1 = up_j.
#define K4 (D_MODEL / 4)
__global__ __launch_bounds__(256) void cvt_weight_pair_kernel(
    const float* __restrict__ wg, const float* __restrict__ wu,
    __half* __restrict__ out)
{
    const size_t i = (size_t)blockIdx.x * 256 + threadIdx.x;   // float4 index
    if (i >= (size_t)MLP_2X * K4) return;
    const size_t n = i / K4;          // interleaved row
    const size_t k4 = i % K4;
    const size_t srow = n >> 1;
    const float4 v = (n & 1) ? ((const float4*)wu)[srow * K4 + k4]
                             : ((const float4*)wg)[srow * K4 + k4];
    store_h4(out, i * 4, v);
}

// ---------------------------------------------------------------------------
// Fused residual-add + RMSNorm; norm output as fp16.
// ---------------------------------------------------------------------------
__global__ __launch_bounds__(256) void rmsnorm_prenorm_kernel(
    const float* __restrict__ x, const float* __restrict__ res_in,
    const float* __restrict__ w, float* __restrict__ res_out,
    __half* __restrict__ nh)
{
    const size_t row = blockIdx.x;
    const int tid = threadIdx.x;
    const float4 xv = ((const float4*)(x      + row * D_MODEL))[tid];
    const float4 rv = ((const float4*)(res_in + row * D_MODEL))[tid];
    float4 s;
    s.x = xv.x + rv.x; s.y = xv.y + rv.y; s.z = xv.z + rv.z; s.w = xv.w + rv.w;
    float ss = s.x * s.x + s.y * s.y + s.z * s.z + s.w * s.w;

    #pragma unroll
    for (int o = 16; o > 0; o >>= 1) ss += __shfl_down_sync(0xffffffffu, ss, o);
    __shared__ float red[8];
    __shared__ float scale_sh;
    if ((tid & 31) == 0) red[tid >> 5] = ss;
    __syncthreads();
    if (tid == 0) {
        float t = 0.f;
        #pragma unroll
        for (int i = 0; i < 8; i++) t += red[i];
        scale_sh = rsqrtf(t / (float)D_MODEL + EPS);
    }
    __syncthreads();
    const float scale = scale_sh;

    ((float4*)(res_out + row * D_MODEL))[tid] = s;
    const float4 wv = ((const float4*)w)[tid];
    float4 o;
    o.x = s.x * scale * wv.x; o.y = s.y * scale * wv.y;
    o.z = s.z * scale * wv.z; o.w = s.w * scale * wv.w;
    store_h4(nh, row * D_MODEL + (size_t)tid * 4, o);
}

// ---------------------------------------------------------------------------
// Causal depthwise conv1d (width 4) + SiLU over the xBC slice (fp16 in/out).
// ---------------------------------------------------------------------------
__global__ __launch_bounds__(256) void conv_silu_kernel(
    const __half* __restrict__ zx, const float* __restrict__ cw,
    const float* __restrict__ cb, __half* __restrict__ out)
{
    const size_t id = (size_t)blockIdx.x * 256 + threadIdx.x;
    if (id >= (size_t)ROWS * CONV_DIM) return;
    const int c = (int)(id % CONV_DIM);
    const size_t r = id / CONV_DIM;
    const int l = (int)(r & (SEQ - 1));
    const __half* base = zx + r * ZX16_W + D_INNER + c;

    const float w0 = cw[c * 4 + 0], w1 = cw[c * 4 + 1];
    const float w2 = cw[c * 4 + 2], w3 = cw[c * 4 + 3];
    float acc = cb[c];
    if (l >= 3) acc += __half2float(base[-3L * ZX16_W]) * w0;
    if (l >= 2) acc += __half2float(base[-2L * ZX16_W]) * w1;
    if (l >= 1) acc += __half2float(base[-1L * ZX16_W]) * w2;
    acc += __half2float(base[0]) * w3;
    out[id] = __float2half(fast_silu(acc));
}

// ---------------------------------------------------------------------------
// Chunked selective scan (R13 math). Phase 1: per-chunk local scan (zero init),
// writes final local state + chunk decay. Grid: (NCHUNK, B*H).
// dtp/dA computed ONCE per timestep (in shared). fp16 global streams.
// ---------------------------------------------------------------------------
#define SCAN_T 8
__global__ __launch_bounds__(128) void scan_local_kernel(
    const __half* __restrict__ conv, const float* __restrict__ dt_in,
    const float* __restrict__ dt_bias, const float* __restrict__ A_log)
{
    const int chunk = blockIdx.x;
    const int bh = blockIdx.y;
    const int b = bh >> 5;
    const int h = bh & 31;
    const int tid = threadIdx.x;
    const int p = tid >> 1;
    const int half = tid & 1;
    const int n0 = half * 64;

    __shared__ float Bs[SCAN_T][STATE];
    __shared__ float xs[SCAN_T][HEADDIM];
    __shared__ float dtps[SCAN_T];
    __shared__ float dAs[SCAN_T];

    float state[64];
    #pragma unroll
    for (int j = 0; j < 64; j++) state[j] = 0.f;
    float cdec = 1.f;

    const float Aneg = -__expf(A_log[h]);
    const float dtb  = dt_bias[h];
    const size_t base_conv = (size_t)b * SEQ * CONV_DIM;
    const int tstart = chunk * CLEN;

    for (int t0 = tstart; t0 < tstart + CLEN; t0 += SCAN_T) {
        __syncthreads();
        for (int idx = tid; idx < SCAN_T * (STATE / 2); idx += 128) {
            const int tt = idx >> 6;
            const int n2 = idx & 63;
            const __half2 hv = *(const __half2*)&conv[
                base_conv + (size_t)(t0 + tt) * CONV_DIM + D_INNER + n2 * 2];
            const float2 fv = __half22float2(hv);
            Bs[tt][n2 * 2]     = fv.x;
            Bs[tt][n2 * 2 + 1] = fv.y;
        }
        for (int idx = tid; idx < SCAN_T * (HEADDIM / 2); idx += 128) {
            const int tt = idx >> 5;
            const int p2 = idx & 31;
            const __half2 hv = *(const __half2*)&conv[
                base_conv + (size_t)(t0 + tt) * CONV_DIM + h * HEADDIM + p2 * 2];
            const float2 fv = __half22float2(hv);
            xs[tt][p2 * 2]     = fv.x;
            xs[tt][p2 * 2 + 1] = fv.y;
        }
        if (tid < SCAN_T) {
            const float draw = dt_in[(size_t)(b * SEQ + t0 + tid) * NHEADS + h] + dtb;
            const float dtp = (draw > 20.f) ? draw : log1pf(__expf(draw));
            dtps[tid] = dtp;
            dAs[tid]  = __expf(dtp * Aneg);
        }
        __syncthreads();

        #pragma unroll 1
        for (int tt = 0; tt < SCAN_T; tt++) {
            const float dA = dAs[tt];
            cdec *= dA;
            const float k = dtps[tt] * xs[tt][p];
            const float4* Bv = (const float4*)&Bs[tt][n0];
            #pragma unroll
            for (int jj = 0; jj < 16; jj++) {
                const float4 bv = Bv[jj];
                float* st = &state[jj * 4];
                st[0] = st[0] * dA + k * bv.x;
                st[1] = st[1] * dA + k * bv.y;
                st[2] = st[2] * dA + k * bv.z;
                st[3] = st[3] * dA + k * bv.w;
            }
        }
    }

    float* dst = g_slocal + ((size_t)(bh * NCHUNK + chunk) * HEADDIM + p) * STATE + n0;
    #pragma unroll
    for (int jj = 0; jj < 16; jj++)
        ((float4*)dst)[jj] = make_float4(state[jj * 4], state[jj * 4 + 1],
                                         state[jj * 4 + 2], state[jj * 4 + 3]);
    if (tid == 0) g_cdec[bh * NCHUNK + chunk] = cdec;
}

// Phase 2: sequential chunk combine (scalar decay per chunk).
// Grid: (B*H, 8 slices) = 512 CTAs; each thread carries 4 elements.
__global__ __launch_bounds__(256) void scan_combine_kernel()
{
    const int bh = blockIdx.x;
    const int slice = blockIdx.y;                 // 0..7
    const int tid = threadIdx.x;
    const int e0 = slice * 1024 + tid;            // element base; +256*j
    float s[4];
    #pragma unroll
    for (int j = 0; j < 4; j++) s[j] = 0.f;

    for (int c = 0; c < NCHUNK; c++) {
        float* dst = g_sin + (size_t)(bh * NCHUNK + c) * (HEADDIM * STATE);
        if (c > 0) {
            const float D = g_cdec[bh * NCHUNK + c - 1];
            const float* src = g_slocal + (size_t)(bh * NCHUNK + c - 1) * (HEADDIM * STATE);
            #pragma unroll
            for (int j = 0; j < 4; j++)
                s[j] = D * s[j] + src[e0 + j * 256];
        }
        #pragma unroll
        for (int j = 0; j < 4; j++)
            dst[e0 + j * 256] = s[j];
    }
}

// Phase 3: per-chunk scan with proper initial state; emits gated y (fp16).
__global__ __launch_bounds__(128) void scan_apply_kernel(
    const __half* __restrict__ conv, const __half* __restrict__ zx,
    const float* __restrict__ dt_in,
    const float* __restrict__ dt_bias, const float* __restrict__ A_log,
    const float* __restrict__ D_param,
    __half* __restrict__ yh)
{
    const int chunk = blockIdx.x;
    const int bh = blockIdx.y;
    const int b = bh >> 5;
    const int h = bh & 31;
    const int tid = threadIdx.x;
    const int p = tid >> 1;
    const int half = tid & 1;
    const int n0 = half * 64;

    __shared__ float Bs[SCAN_T][STATE];
    __shared__ float Cs[SCAN_T][STATE];
    __shared__ float xs[SCAN_T][HEADDIM];
    __shared__ float zs[SCAN_T][HEADDIM];
    __shared__ float dtps[SCAN_T];
    __shared__ float dAs[SCAN_T];

    float state[64];
    {
        const float* src = g_sin + ((size_t)(bh * NCHUNK + chunk) * HEADDIM + p) * STATE + n0;
        #pragma unroll
        for (int jj = 0; jj < 16; jj++) {
            const float4 v = ((const float4*)src)[jj];
            state[jj * 4] = v.x; state[jj * 4 + 1] = v.y;
            state[jj * 4 + 2] = v.z; state[jj * 4 + 3] = v.w;
        }
    }

    const float Aneg = -__expf(A_log[h]);
    const float dtb  = dt_bias[h];
    const float Dp   = D_param[h];
    const size_t base_conv = (size_t)b * SEQ * CONV_DIM;
    const size_t base_z    = (size_t)b * SEQ * ZX16_W;
    const int tstart = chunk * CLEN;

    for (int t0 = tstart; t0 < tstart + CLEN; t0 += SCAN_T) {
        __syncthreads();
        for (int idx = tid; idx < SCAN_T * (STATE / 2); idx += 128) {
            const int tt = idx >> 6;
            const int n2 = idx & 63;
            const size_t rowp = base_conv + (size_t)(t0 + tt) * CONV_DIM;
            const float2 bf = __half22float2(
                *(const __half2*)&conv[rowp + D_INNER + n2 * 2]);
            const float2 cf = __half22float2(
                *(const __half2*)&conv[rowp + D_INNER + STATE + n2 * 2]);
            Bs[tt][n2 * 2]     = bf.x;
            Bs[tt][n2 * 2 + 1] = bf.y;
            Cs[tt][n2 * 2]     = cf.x;
            Cs[tt][n2 * 2 + 1] = cf.y;
        }
        for (int idx = tid; idx < SCAN_T * (HEADDIM / 2); idx += 128) {
            const int tt = idx >> 5;
            const int p2 = idx & 31;
            const float2 xf = __half22float2(*(const __half2*)&conv[
                base_conv + (size_t)(t0 + tt) * CONV_DIM + h * HEADDIM + p2 * 2]);
            const float2 zf = __half22float2(*(const __half2*)&zx[
                base_z + (size_t)(t0 + tt) * ZX16_W + h * HEADDIM + p2 * 2]);
            xs[tt][p2 * 2]     = xf.x;
            xs[tt][p2 * 2 + 1] = xf.y;
            zs[tt][p2 * 2]     = zf.x;
            zs[tt][p2 * 2 + 1] = zf.y;
        }
        if (tid < SCAN_T) {
            const float draw = dt_in[(size_t)(b * SEQ + t0 + tid) * NHEADS + h] + dtb;
            const float dtp = (draw > 20.f) ? draw : log1pf(__expf(draw));
            dtps[tid] = dtp;
            dAs[tid]  = __expf(dtp * Aneg);
        }
        __syncthreads();

        #pragma unroll 1
        for (int tt = 0; tt < SCAN_T; tt++) {
            const float dA = dAs[tt];
            const float xv = xs[tt][p];
            const float k = dtps[tt] * xv;
            float y0 = 0.f, y1 = 0.f, y2 = 0.f, y3 = 0.f;
            const float4* Bv = (const float4*)&Bs[tt][n0];
            const float4* Cv = (const float4*)&Cs[tt][n0];
            #pragma unroll
            for (int jj = 0; jj < 16; jj++) {
                const float4 bv = Bv[jj];
                const float4 cv = Cv[jj];
                float* st = &state[jj * 4];
                st[0] = st[0] * dA + k * bv.x; y0 += st[0] * cv.x;
                st[1] = st[1] * dA + k * bv.y; y1 += st[1] * cv.y;
                st[2] = st[2] * dA + k * bv.z; y2 += st[2] * cv.z;
                st[3] = st[3] * dA + k * bv.w; y3 += st[3] * cv.w;
            }
            float y = (y0 + y1) + (y2 + y3);
            y += __shfl_xor_sync(0xffffffffu, y, 1);
            if (half == 0) {
                const float gate = fast_silu(zs[tt][p]);
                const float yo = (y + Dp * xv) * gate;
                yh[((size_t)(b * SEQ + t0 + tt)) * D_INNER + h * HEADDIM + p] =
                    __float2half(yo);
            }
        }
    }
}

// ---------------------------------------------------------------------------
// Launch
// ---------------------------------------------------------------------------
extern "C" void kernel_launch(void* const* d_in, const int* in_sizes, int n_in,
                              void* d_out, int out_size)
{
    const float* hidden     = (const float*)d_in[0];
    const float* residual   = (const float*)d_in[1];
    const float* ssm_norm_w = (const float*)d_in[2];
    const float* mlp_norm_w = (const float*)d_in[3];
    const float* in_proj_w  = (const float*)d_in[4];
    const float* conv_w     = (const float*)d_in[5];
    const float* conv_b     = (const float*)d_in[6];
    const float* dt_bias    = (const float*)d_in[7];
    const float* A_log      = (const float*)d_in[8];
    const float* D_param    = (const float*)d_in[9];
    const float* out_proj_w = (const float*)d_in[10];
    const float* mlp_gate_w = (const float*)d_in[11];
    const float* mlp_up_w   = (const float*)d_in[12];
    const float* mlp_down_w = (const float*)d_in[13];

    float* out_h   = (float*)d_out;
    float* out_res = out_h + (size_t)ROWS * D_MODEL;

    void *p_res1, *p_h2, *p_dt;
    void *p_zx16, *p_cv16, *p_n, *p_y, *p_a;
    void *p_wi, *p_wo, *p_wm, *p_wd;
    cudaGetSymbolAddress(&p_res1, g_res1);
    cudaGetSymbolAddress(&p_h2,   g_h2);
    cudaGetSymbolAddress(&p_dt,   g_dt);
    cudaGetSymbolAddress(&p_zx16, g_zx16);
    cudaGetSymbolAddress(&p_cv16, g_cv16);
    cudaGetSymbolAddress(&p_n,    g_norm);
    cudaGetSymbolAddress(&p_y,    g_y);
    cudaGetSymbolAddress(&p_a,    g_act);
    cudaGetSymbolAddress(&p_wi,   g_wi);
    cudaGetSymbolAddress(&p_wo,   g_wo);
    cudaGetSymbolAddress(&p_wm,   g_wm);
    cudaGetSymbolAddress(&p_wd,   g_wd);

    cudaFuncSetAttribute(gemm_f16<0>,
                         cudaFuncAttributeMaxDynamicSharedMemorySize, GEMM_SMEM);
    cudaFuncSetAttribute(gemm_f16<1>,
                         cudaFuncAttributeMaxDynamicSharedMemorySize, GEMM_SMEM);
    cudaFuncSetAttribute(gemm_f16<2>,
                         cudaFuncAttributeMaxDynamicSharedMemorySize, GEMM_SMEM);

    // Weight conversions (fp16, padding / interleave)
    {
        size_t nr, nt;
        nr = (size_t)D_IN_PROJ * D_MODEL / 4; nt = (size_t)N_INPROJ_PAD * D_MODEL / 4;
        cvt_weight_kernel<<<(unsigned)((nt + 255) / 256), 256>>>(
            in_proj_w, (__half*)p_wi, nr, nt);
        nr = nt = (size_t)D_MODEL * D_INNER / 4;
        cvt_weight_kernel<<<(unsigned)((nt + 255) / 256), 256>>>(
            out_proj_w, (__half*)p_wo, nr, nt);
        nt = (size_t)MLP_2X * D_MODEL / 4;
        cvt_weight_pair_kernel<<<(unsigned)((nt + 255) / 256), 256>>>(
            mlp_gate_w, mlp_up_w, (__half*)p_wm);
        nr = nt = (size_t)D_MODEL * MLP_INNER / 4;
        cvt_weight_kernel<<<(unsigned)((nt + 255) / 256), 256>>>(
            mlp_down_w, (__half*)p_wd, nr, nt);
    }

    // 1) prenorm RMSNorm #1
    rmsnorm_prenorm_kernel<<<ROWS, 256>>>(hidden, residual, ssm_norm_w,
        (float*)p_res1, (__half*)p_n);
    // 2) in_proj -> fp16 z+xBC, fp32 dt
    gemm_f16<2><<<dim3(N_INPROJ_PAD / 256, ROWS / 128), 512, GEMM_SMEM>>>(
        (const __half*)p_n, (const __half*)p_wi,
        nullptr, (__half*)p_zx16, (float*)p_dt, ROWS, N_INPROJ_PAD, D_MODEL);
    // 3) causal depthwise conv + SiLU (fp16 in/out)
    conv_silu_kernel<<<(unsigned)(((size_t)ROWS * CONV_DIM + 255) / 256), 256>>>(
        (const __half*)p_zx16, conv_w, conv_b, (__half*)p_cv16);
    // 4) chunked selective scan (3 phases)
    scan_local_kernel<<<dim3(NCHUNK, BATCH * NHEADS), 128>>>(
        (const __half*)p_cv16, (const float*)p_dt, dt_bias, A_log);
    scan_combine_kernel<<<dim3(BATCH * NHEADS, 8), 256>>>();
    scan_apply_kernel<<<dim3(NCHUNK, BATCH * NHEADS), 128>>>(
        (const __half*)p_cv16, (const __half*)p_zx16, (const float*)p_dt,
        dt_bias, A_log, D_param, (__half*)p_y);
    // 5) out_proj
    gemm_f16<0><<<dim3(D_MODEL / 256, ROWS / 128), 512, GEMM_SMEM>>>(
        (const __half*)p_y, (const __half*)p_wo,
        (float*)p_h2, nullptr, nullptr, ROWS, D_MODEL, D_INNER);
    // 6) prenorm RMSNorm #2
    rmsnorm_prenorm_kernel<<<ROWS, 256>>>((const float*)p_h2, (const float*)p_res1,
        mlp_norm_w, out_res, (__half*)p_n);
    // 7) fused MLP gate+up GEMM with SwiGLU epilogue (interleaved weights)
    gemm_f16<1><<<dim3(MLP_2X / 256, ROWS / 128), 512, GEMM_SMEM>>>(
        (const __half*)p_n, (const __half*)p_wm,
        nullptr, (__half*)p_a, nullptr, ROWS, MLP_2X, D_MODEL);
    // 8) down projection -> first model output
    gemm_f16<0><<<dim3(D_MODEL / 256, ROWS / 128), 512, GEMM_SMEM>>>(
        (const __half*)p_a, (const __half*)p_wd,
        out_h, nullptr, nullptr, ROWS, D_MODEL, MLP_INNER);
}

// round 17
// speedup vs baseline: 1.1400x; 1.0736x over previous
#include <cuda_runtime.h>
#include <cuda_bf16.h>
#include <cuda_fp16.h>
#include <math.h>
#include <stdint.h>

// ---------------------------------------------------------------------------
// Problem constants
// ---------------------------------------------------------------------------
#define BATCH     2
#define SEQ       4096
#define ROWS      (BATCH * SEQ)          // 8192 tokens
#define D_MODEL   1024
#define STATE     128
#define HEADDIM   64
#define D_INNER   2048
#define NHEADS    32
#define CONV_DIM  (D_INNER + 2 * STATE)  // 2304
#define D_IN_PROJ (2 * D_INNER + 2 * STATE + NHEADS) // 4384
#define ZX16_W    (D_INNER + CONV_DIM)   // 4352 fp16 cols (z + xBC)
#define N_INPROJ_PAD 4608                // padded to multiple of 256
#define MLP_INNER 4096
#define MLP_2X    (2 * MLP_INNER)        // interleaved gate/up
#define EPS       1e-5f
#define NCHUNK    32
#define CLEN      128                    // SEQ / NCHUNK

// ---------------------------------------------------------------------------
// Scratch (static device arrays; no runtime allocation allowed)
// ---------------------------------------------------------------------------
__device__ float g_res1  [(size_t)ROWS * D_MODEL];
__device__ float g_h2    [(size_t)ROWS * D_MODEL];
__device__ float g_dt    [(size_t)ROWS * NHEADS];          // fp32 dt (precision)

__device__ float g_slocal[(size_t)BATCH * NHEADS * NCHUNK * HEADDIM * STATE];
__device__ float g_sin   [(size_t)BATCH * NHEADS * NCHUNK * HEADDIM * STATE];
__device__ float g_cdec  [BATCH * NHEADS * NCHUNK];
__device__ float g_qpre  [(size_t)BATCH * NHEADS * NCHUNK * CLEN];  // inclusive decay prefix

__device__ __half g_zx16 [(size_t)ROWS * ZX16_W];          // z + xBC, fp16
__device__ __half g_cv16 [(size_t)ROWS * CONV_DIM];        // conv output, fp16
__device__ __half g_norm [(size_t)ROWS * D_MODEL];
__device__ __half g_y    [(size_t)ROWS * D_INNER];         // y_local, then final gated y
__device__ __half g_act  [(size_t)ROWS * MLP_INNER];

__device__ __half g_wi[(size_t)N_INPROJ_PAD * D_MODEL];
__device__ __half g_wo[(size_t)D_MODEL * D_INNER];
__device__ __half g_wm[(size_t)MLP_2X * D_MODEL];   // interleaved gate/up
__device__ __half g_wd[(size_t)D_MODEL * MLP_INNER];

// ---------------------------------------------------------------------------
// PTX helpers (baseline sm_103: cp.async + ldmatrix + mma.sync)
// ---------------------------------------------------------------------------
__device__ __forceinline__ uint32_t smem_u32(const void* p) {
    uint32_t a;
    asm("{ .reg .u64 t; cvta.to.shared.u64 t, %1; cvt.u32.u64 %0, t; }"
        : "=r"(a) : "l"(p));
    return a;
}
__device__ __forceinline__ void cp_async16(uint32_t dst, const void* src) {
    asm volatile("cp.async.cg.shared.global [%0], [%1], 16;\n" :: "r"(dst), "l"(src));
}
__device__ __forceinline__ void cp_commit() {
    asm volatile("cp.async.commit_group;\n" ::: "memory");
}
template <int N>
__device__ __forceinline__ void cp_wait() {
    asm volatile("cp.async.wait_group %0;\n" :: "n"(N) : "memory");
}
__device__ __forceinline__ void ldmx4(uint32_t* r, uint32_t addr) {
    asm volatile("ldmatrix.sync.aligned.m8n8.x4.shared.b16 {%0,%1,%2,%3}, [%4];"
                 : "=r"(r[0]), "=r"(r[1]), "=r"(r[2]), "=r"(r[3]) : "r"(addr));
}
__device__ __forceinline__ void mma_f16(float* c, const uint32_t* a, const uint32_t* b) {
    asm volatile(
        "mma.sync.aligned.m16n8k16.row.col.f32.f16.f16.f32 "
        "{%0,%1,%2,%3}, {%4,%5,%6,%7}, {%8,%9}, {%0,%1,%2,%3};"
        : "+f"(c[0]), "+f"(c[1]), "+f"(c[2]), "+f"(c[3])
        : "r"(a[0]), "r"(a[1]), "r"(a[2]), "r"(a[3]), "r"(b[0]), "r"(b[1]));
}
__device__ __forceinline__ float fast_silu(float x) {
    return __fdividef(x, 1.f + __expf(-x));
}

// ---------------------------------------------------------------------------
// fp16 tensor-core GEMM: C[M,N] = A[M,K] @ W[N,K]^T, fp32 accumulate.
// 128x256 CTA tile, BK=32, 512 threads (16 warps, 32x64 each), 4 stages.
// MODE 0: fp32 C.  MODE 1: SwiGLU epilogue (interleaved gate/up -> fp16 Out).
// MODE 2: in_proj split epilogue: cols<ZX16_W -> fp16 OutH (width ZX16_W),
//         cols in [ZX16_W, D_IN_PROJ) -> fp32 dt buffer (width NHEADS).
// ---------------------------------------------------------------------------
#define GSTAGE   4
#define ROWB     80
#define A_TILE_B (128 * ROWB)            // 10240
#define W_TILE_B (256 * ROWB)            // 20480
#define STAGE_B  (A_TILE_B + W_TILE_B)   // 30720
#define GEMM_SMEM (GSTAGE * STAGE_B)     // 122880

__device__ __forceinline__ void load_stage_g(
    uint32_t sbase,
    const __half* __restrict__ A, const __half* __restrict__ W,
    int bm, int bn, int K, int kc, int tid)
{
    const int koff = kc * 32;
    {
        const int row = tid >> 2, ch = tid & 3;
        const uint32_t d = (uint32_t)(row * ROWB + ch * 16);
        cp_async16(sbase + d, A + (size_t)(bm + row) * K + koff + ch * 8);
    }
    #pragma unroll
    for (int i = 0; i < 2; i++) {
        const int slot = tid + i * 512;
        const int row = slot >> 2, ch = slot & 3;
        const uint32_t d = (uint32_t)(row * ROWB + ch * 16);
        cp_async16(sbase + A_TILE_B + d, W + (size_t)(bn + row) * K + koff + ch * 8);
    }
}

template <int MODE>
__global__ __launch_bounds__(512, 1)
void gemm_f16(const __half* __restrict__ A,
              const __half* __restrict__ W,
              float* __restrict__ C,
              __half* __restrict__ Out,
              float* __restrict__ Dt,
              int M, int N, int K)
{
    extern __shared__ __align__(128) char dynsmem[];
    const uint32_t sbase = smem_u32(dynsmem);

    const int tid  = threadIdx.x;
    const int lane = tid & 31;
    const int wid  = tid >> 5;
    const int wm   = wid & 3;             // 4 m-groups of 32 rows
    const int wn   = wid >> 2;            // 4 n-groups of 64 cols
    const int bm   = blockIdx.y * 128;
    const int bn   = blockIdx.x * 256;

    const uint32_t a_off = (uint32_t)((wm * 32 + (lane & 15)) * ROWB
                                      + ((lane >> 4) & 1) * 16);
    const uint32_t b_off = (uint32_t)((wn * 64 + ((lane >> 4) & 1) * 8 + (lane & 7)) * ROWB
                                      + ((lane >> 3) & 1) * 16);

    float acc[2][8][4];
    #pragma unroll
    for (int i = 0; i < 2; i++)
        #pragma unroll
        for (int j = 0; j < 8; j++)
            #pragma unroll
            for (int q = 0; q < 4; q++) acc[i][j][q] = 0.f;

    const int nk = K >> 5;

    load_stage_g(sbase + 0 * STAGE_B, A, W, bm, bn, K, 0, tid);
    cp_commit();
    load_stage_g(sbase + 1 * STAGE_B, A, W, bm, bn, K, 1, tid);
    cp_commit();
    load_stage_g(sbase + 2 * STAGE_B, A, W, bm, bn, K, 2, tid);
    cp_commit();

    for (int k = 0; k < nk; k++) {
        const uint32_t stb = sbase + (uint32_t)(k % GSTAGE) * STAGE_B;
        cp_wait<2>();
        __syncthreads();

        const int kn = k + 3;
        if (kn < nk)
            load_stage_g(sbase + (uint32_t)(kn % GSTAGE) * STAGE_B,
                         A, W, bm, bn, K, kn, tid);
        cp_commit();

        const uint32_t a_b = stb + a_off;
        const uint32_t b_b = stb + A_TILE_B + b_off;

        #pragma unroll
        for (int s = 0; s < 2; s++) {
            const uint32_t kb = (uint32_t)(s * 32);
            uint32_t af[2][4];
            #pragma unroll
            for (int i = 0; i < 2; i++)
                ldmx4(af[i], a_b + (uint32_t)(i * 16 * ROWB) + kb);
            #pragma unroll
            for (int jp = 0; jp < 4; jp++) {
                uint32_t wf[4];
                ldmx4(wf, b_b + (uint32_t)(jp * 16 * ROWB) + kb);
                #pragma unroll
                for (int i = 0; i < 2; i++)
                    #pragma unroll
                    for (int f = 0; f < 2; f++)
                        mma_f16(acc[i][jp * 2 + f], af[i], wf + f * 2);
            }
        }
    }

    #pragma unroll
    for (int i = 0; i < 2; i++) {
        const int row0 = bm + wm * 32 + i * 16 + (lane >> 2);
        #pragma unroll
        for (int j = 0; j < 8; j++) {
            const int col = bn + wn * 64 + j * 8 + (lane & 3) * 2;
            if (MODE == 0) {
                if (col < N) {
                    *(float2*)&C[(size_t)row0 * N + col] =
                        make_float2(acc[i][j][0], acc[i][j][1]);
                    *(float2*)&C[(size_t)(row0 + 8) * N + col] =
                        make_float2(acc[i][j][2], acc[i][j][3]);
                }
            } else if (MODE == 1) {
                const int NO = N >> 1;
                const int colc = col >> 1;
                {
                    const float v = fast_silu(acc[i][j][0]) * acc[i][j][1];
                    Out[(size_t)row0 * NO + colc] = __float2half(v);
                }
                {
                    const float v = fast_silu(acc[i][j][2]) * acc[i][j][3];
                    Out[(size_t)(row0 + 8) * NO + colc] = __float2half(v);
                }
            } else {  // MODE 2: in_proj split
                if (col < ZX16_W) {
                    __half2 v0; v0.x = __float2half(acc[i][j][0]);
                                v0.y = __float2half(acc[i][j][1]);
                    __half2 v1; v1.x = __float2half(acc[i][j][2]);
                                v1.y = __float2half(acc[i][j][3]);
                    *(__half2*)&Out[(size_t)row0 * ZX16_W + col]       = v0;
                    *(__half2*)&Out[(size_t)(row0 + 8) * ZX16_W + col] = v1;
                } else if (col < D_IN_PROJ) {
                    const int dc = col - ZX16_W;
                    *(float2*)&Dt[(size_t)row0 * NHEADS + dc] =
                        make_float2(acc[i][j][0], acc[i][j][1]);
                    *(float2*)&Dt[(size_t)(row0 + 8) * NHEADS + dc] =
                        make_float2(acc[i][j][2], acc[i][j][3]);
                }
            }
        }
    }
}

// ---------------------------------------------------------------------------
// fp16 helpers
// ---------------------------------------------------------------------------
__device__ __forceinline__ void store_h4(__half* __restrict__ p, size_t off, float4 v) {
    __half2 a; a.x = __float2half(v.x); a.y = __float2half(v.y);
    __half2 b; b.x = __float2half(v.z); b.y = __float2half(v.w);
    *(__half2*)(p + off)     = a;
    *(__half2*)(p + off + 2) = b;
}

// Weight fp32 -> fp16, float4-vectorized, zero tail padding.
__global__ __launch_bounds__(256) void cvt_weight_kernel(
    const float* __restrict__ w, __half* __restrict__ out,
    size_t n_real4, size_t n_total4)
{
    const size_t i = (size_t)blockIdx.x * 256 + threadIdx.x;
    if (i >= n_total4) return;
    float4 v = (i < n_real4) ? ((const float4*)w)[i]
                             : make_float4(0.f, 0.f, 0.f, 0.f);
    store_h4(out, i * 4, v);
}

// gate/up weights -> row-interleaved fp16: row 2j = gate_j, 2j+1 = up_j.
#define K4 (D_MODEL / 4)
__global__ __launch_bounds__(256) void cvt_weight_pair_kernel(
    const float* __restrict__ wg, const float* __restrict__ wu,
    __half* __restrict__ out)
{
    const size_t i = (size_t)blockIdx.x * 256 + threadIdx.x;   // float4 index
    if (i >= (size_t)MLP_2X * K4) return;
    const size_t n = i / K4;          // interleaved row
    const size_t k4 = i % K4;
    const size_t srow = n >> 1;
    const float4 v = (n & 1) ? ((const float4*)wu)[srow * K4 + k4]
                             : ((const float4*)wg)[srow * K4 + k4];
    store_h4(out, i * 4, v);
}

// ---------------------------------------------------------------------------
// Fused residual-add + RMSNorm; norm output as fp16.
// ---------------------------------------------------------------------------
__global__ __launch_bounds__(256) void rmsnorm_prenorm_kernel(
    const float* __restrict__ x, const float* __restrict__ res_in,
    const float* __restrict__ w, float* __restrict__ res_out,
    __half* __restrict__ nh)
{
    const size_t row = blockIdx.x;
    const int tid = threadIdx.x;
    const float4 xv = ((const float4*)(x      + row * D_MODEL))[tid];
    const float4 rv = ((const float4*)(res_in + row * D_MODEL))[tid];
    float4 s;
    s.x = xv.x + rv.x; s.y = xv.y + rv.y; s.z = xv.z + rv.z; s.w = xv.w + rv.w;
    float ss = s.x * s.x + s.y * s.y + s.z * s.z + s.w * s.w;

    #pragma unroll
    for (int o = 16; o > 0; o >>= 1) ss += __shfl_down_sync(0xffffffffu, ss, o);
    __shared__ float red[8];
    __shared__ float scale_sh;
    if ((tid & 31) == 0) red[tid >> 5] = ss;
    __syncthreads();
    if (tid == 0) {
        float t = 0.f;
        #pragma unroll
        for (int i = 0; i < 8; i++) t += red[i];
        scale_sh = rsqrtf(t / (float)D_MODEL + EPS);
    }
    __syncthreads();
    const float scale = scale_sh;

    ((float4*)(res_out + row * D_MODEL))[tid] = s;
    const float4 wv = ((const float4*)w)[tid];
    float4 o;
    o.x = s.x * scale * wv.x; o.y = s.y * scale * wv.y;
    o.z = s.z * scale * wv.z; o.w = s.w * scale * wv.w;
    store_h4(nh, row * D_MODEL + (size_t)tid * 4, o);
}

// ---------------------------------------------------------------------------
// Causal depthwise conv1d (width 4) + SiLU over the xBC slice (fp16 in/out).
// ---------------------------------------------------------------------------
__global__ __launch_bounds__(256) void conv_silu_kernel(
    const __half* __restrict__ zx, const float* __restrict__ cw,
    const float* __restrict__ cb, __half* __restrict__ out)
{
    const size_t id = (size_t)blockIdx.x * 256 + threadIdx.x;
    if (id >= (size_t)ROWS * CONV_DIM) return;
    const int c = (int)(id % CONV_DIM);
    const size_t r = id / CONV_DIM;
    const int l = (int)(r & (SEQ - 1));
    const __half* base = zx + r * ZX16_W + D_INNER + c;

    const float w0 = cw[c * 4 + 0], w1 = cw[c * 4 + 1];
    const float w2 = cw[c * 4 + 2], w3 = cw[c * 4 + 3];
    float acc = cb[c];
    if (l >= 3) acc += __half2float(base[-3L * ZX16_W]) * w0;
    if (l >= 2) acc += __half2float(base[-2L * ZX16_W]) * w1;
    if (l >= 1) acc += __half2float(base[-1L * ZX16_W]) * w2;
    acc += __half2float(base[0]) * w3;
    out[id] = __float2half(fast_silu(acc));
}

// ---------------------------------------------------------------------------
// Phase 1: per-chunk local scan (zero init) + LOCAL y dot.
// Stores: y_local (un-gated, fp16) to g_y, final local state, chunk decay,
// and the inclusive per-step decay prefix g_qpre. Grid: (NCHUNK, B*H).
// ---------------------------------------------------------------------------
#define SCAN_T 8
__global__ __launch_bounds__(128) void scan_localy_kernel(
    const __half* __restrict__ conv, const float* __restrict__ dt_in,
    const float* __restrict__ dt_bias, const float* __restrict__ A_log,
    __half* __restrict__ ylocal)
{
    const int chunk = blockIdx.x;
    const int bh = blockIdx.y;
    const int b = bh >> 5;
    const int h = bh & 31;
    const int tid = threadIdx.x;
    const int p = tid >> 1;
    const int half = tid & 1;
    const int n0 = half * 64;

    __shared__ float Bs[SCAN_T][STATE];
    __shared__ float Cs[SCAN_T][STATE];
    __shared__ float xs[SCAN_T][HEADDIM];
    __shared__ float dtps[SCAN_T];
    __shared__ float dAs[SCAN_T];

    float state[64];
    #pragma unroll
    for (int j = 0; j < 64; j++) state[j] = 0.f;
    float cdec = 1.f;

    const float Aneg = -__expf(A_log[h]);
    const float dtb  = dt_bias[h];
    const size_t base_conv = (size_t)b * SEQ * CONV_DIM;
    const int tstart = chunk * CLEN;
    float* qpre = g_qpre + (size_t)(bh * NCHUNK + chunk) * CLEN;

    for (int lt = 0; lt < CLEN; lt += SCAN_T) {
        __syncthreads();
        for (int idx = tid; idx < SCAN_T * (STATE / 2); idx += 128) {
            const int tt = idx >> 6;
            const int n2 = idx & 63;
            const size_t rowp = base_conv + (size_t)(tstart + lt + tt) * CONV_DIM;
            const float2 bf = __half22float2(
                *(const __half2*)&conv[rowp + D_INNER + n2 * 2]);
            const float2 cf = __half22float2(
                *(const __half2*)&conv[rowp + D_INNER + STATE + n2 * 2]);
            Bs[tt][n2 * 2]     = bf.x;
            Bs[tt][n2 * 2 + 1] = bf.y;
            Cs[tt][n2 * 2]     = cf.x;
            Cs[tt][n2 * 2 + 1] = cf.y;
        }
        for (int idx = tid; idx < SCAN_T * (HEADDIM / 2); idx += 128) {
            const int tt = idx >> 5;
            const int p2 = idx & 31;
            const float2 fv = __half22float2(*(const __half2*)&conv[
                base_conv + (size_t)(tstart + lt + tt) * CONV_DIM + h * HEADDIM + p2 * 2]);
            xs[tt][p2 * 2]     = fv.x;
            xs[tt][p2 * 2 + 1] = fv.y;
        }
        if (tid < SCAN_T) {
            const float draw = dt_in[(size_t)(b * SEQ + tstart + lt + tid) * NHEADS + h] + dtb;
            const float dtp = (draw > 20.f) ? draw : log1pf(__expf(draw));
            dtps[tid] = dtp;
            dAs[tid]  = __expf(dtp * Aneg);
        }
        __syncthreads();

        #pragma unroll 1
        for (int tt = 0; tt < SCAN_T; tt++) {
            const float dA = dAs[tt];
            cdec *= dA;
            if (tid == 0) qpre[lt + tt] = cdec;
            const float xv = xs[tt][p];
            const float k = dtps[tt] * xv;
            float y0 = 0.f, y1 = 0.f, y2 = 0.f, y3 = 0.f;
            const float4* Bv = (const float4*)&Bs[tt][n0];
            const float4* Cv = (const float4*)&Cs[tt][n0];
            #pragma unroll
            for (int jj = 0; jj < 16; jj++) {
                const float4 bv = Bv[jj];
                const float4 cv = Cv[jj];
                float* st = &state[jj * 4];
                st[0] = st[0] * dA + k * bv.x; y0 += st[0] * cv.x;
                st[1] = st[1] * dA + k * bv.y; y1 += st[1] * cv.y;
                st[2] = st[2] * dA + k * bv.z; y2 += st[2] * cv.z;
                st[3] = st[3] * dA + k * bv.w; y3 += st[3] * cv.w;
            }
            float y = (y0 + y1) + (y2 + y3);
            y += __shfl_xor_sync(0xffffffffu, y, 1);
            if (half == 0)
                ylocal[((size_t)(b * SEQ + tstart + lt + tt)) * D_INNER
                       + h * HEADDIM + p] = __float2half(y);
        }
    }

    float* dst = g_slocal + ((size_t)(bh * NCHUNK + chunk) * HEADDIM + p) * STATE + n0;
    #pragma unroll
    for (int jj = 0; jj < 16; jj++)
        ((float4*)dst)[jj] = make_float4(state[jj * 4], state[jj * 4 + 1],
                                         state[jj * 4 + 2], state[jj * 4 + 3]);
    if (tid == 0) g_cdec[bh * NCHUNK + chunk] = cdec;
}

// Phase 2: sequential chunk combine (scalar decay per chunk).
// Grid: (B*H, 8 slices) = 512 CTAs; each thread carries 4 elements.
__global__ __launch_bounds__(256) void scan_combine_kernel()
{
    const int bh = blockIdx.x;
    const int slice = blockIdx.y;                 // 0..7
    const int tid = threadIdx.x;
    const int e0 = slice * 1024 + tid;            // element base; +256*j
    float s[4];
    #pragma unroll
    for (int j = 0; j < 4; j++) s[j] = 0.f;

    for (int c = 0; c < NCHUNK; c++) {
        float* dst = g_sin + (size_t)(bh * NCHUNK + c) * (HEADDIM * STATE);
        if (c > 0) {
            const float D = g_cdec[bh * NCHUNK + c - 1];
            const float* src = g_slocal + (size_t)(bh * NCHUNK + c - 1) * (HEADDIM * STATE);
            #pragma unroll
            for (int j = 0; j < 4; j++)
                s[j] = D * s[j] + src[e0 + j * 256];
        }
        #pragma unroll
        for (int j = 0; j < 4; j++)
            dst[e0 + j * 256] = s[j];
    }
}

// ---------------------------------------------------------------------------
// Phase 3: tensor-core correction + gating.
//   corr[t,p] = (qpre_t * C_t) . S_init[p,:]   (128x64x128 mma per chunk-head)
//   y = (y_local + corr + Dp*x) * silu(z) -> fp16 (in-place on g_y)
// Grid (NCHUNK, B*H), 128 threads. Dynamic smem: A 128 rows + B 64 rows @272B.
// ---------------------------------------------------------------------------
#define CR_ROWB 272
#define CR_SMEM ((128 + 64) * CR_ROWB)   // 52224 B

__global__ __launch_bounds__(128) void scan_correct_kernel(
    const __half* __restrict__ conv, const __half* __restrict__ zx,
    const float* __restrict__ D_param, __half* __restrict__ y)
{
    extern __shared__ __align__(128) char crsmem[];
    __shared__ float qs[CLEN];

    const int chunk = blockIdx.x;
    const int bh = blockIdx.y;
    const int b = bh >> 5;
    const int h = bh & 31;
    const int tid = threadIdx.x;
    const int lane = tid & 31;
    const int wid = tid >> 5;            // 4 warps, each 32 rows x 64 cols

    const uint32_t sA = smem_u32(crsmem);
    const uint32_t sB = sA + 128 * CR_ROWB;
    const size_t base_conv = (size_t)b * SEQ * CONV_DIM;
    const size_t base_z    = (size_t)b * SEQ * ZX16_W;
    const int tstart = chunk * CLEN;

    qs[tid] = g_qpre[(size_t)(bh * NCHUNK + chunk) * CLEN + tid];
    __syncthreads();

    // A tile: row t, cols n -> qpre_t * C_t[n], fp16
    {
        const float q = qs[tid];
        const __half2* src = (const __half2*)&conv[
            base_conv + (size_t)(tstart + tid) * CONV_DIM + D_INNER + STATE];
        __half2* dst = (__half2*)(crsmem + tid * CR_ROWB);
        #pragma unroll 8
        for (int n2 = 0; n2 < 64; n2++) {
            const float2 f = __half22float2(src[n2]);
            __half2 o; o.x = __float2half(q * f.x); o.y = __float2half(q * f.y);
            dst[n2] = o;
        }
    }
    // B tile: row p, cols n -> S_init[p][n] fp16 (from fp32 g_sin)
    {
        const float* src = g_sin + (size_t)(bh * NCHUNK + chunk) * (HEADDIM * STATE);
        for (int idx = tid; idx < HEADDIM * (STATE / 4); idx += 128) {
            const int row = idx >> 5;          // 0..63
            const int n4  = idx & 31;          // float4 index
            const float4 v = ((const float4*)src)[row * 32 + n4];
            __half2 o0; o0.x = __float2half(v.x); o0.y = __float2half(v.y);
            __half2 o1; o1.x = __float2half(v.z); o1.y = __float2half(v.w);
            __half2* dst = (__half2*)(crsmem + 128 * CR_ROWB + row * CR_ROWB + n4 * 8);
            dst[0] = o0; dst[1] = o1;
        }
    }
    __syncthreads();

    const uint32_t a_off = sA + (uint32_t)((wid * 32 + (lane & 15)) * CR_ROWB
                                           + ((lane >> 4) & 1) * 16);
    const uint32_t b_off = sB + (uint32_t)((((lane >> 4) & 1) * 8 + (lane & 7)) * CR_ROWB
                                           + ((lane >> 3) & 1) * 16);

    float acc[2][8][4];
    #pragma unroll
    for (int i = 0; i < 2; i++)
        #pragma unroll
        for (int j = 0; j < 8; j++)
            #pragma unroll
            for (int q = 0; q < 4; q++) acc[i][j][q] = 0.f;

    #pragma unroll
    for (int k16 = 0; k16 < 8; k16++) {
        const uint32_t kb = (uint32_t)(k16 * 32);
        uint32_t af[2][4];
        #pragma unroll
        for (int i = 0; i < 2; i++)
            ldmx4(af[i], a_off + (uint32_t)(i * 16 * CR_ROWB) + kb);
        #pragma unroll
        for (int jp = 0; jp < 4; jp++) {
            uint32_t wf[4];
            ldmx4(wf, b_off + (uint32_t)(jp * 16 * CR_ROWB) + kb);
            #pragma unroll
            for (int i = 0; i < 2; i++)
                #pragma unroll
                for (int f = 0; f < 2; f++)
                    mma_f16(acc[i][jp * 2 + f], af[i], wf + f * 2);
        }
    }

    // Epilogue: y = (y_local + corr + Dp*x) * silu(z)
    const float Dp = D_param[h];
    #pragma unroll
    for (int i = 0; i < 2; i++) {
        const int trow = wid * 32 + i * 16 + (lane >> 2);
        #pragma unroll
        for (int j = 0; j < 8; j++) {
            const int col = j * 8 + (lane & 3) * 2;
            #pragma unroll
            for (int q = 0; q < 2; q++) {
                const int t = tstart + trow + q * 8;
                const size_t tok = (size_t)(b * SEQ + t);
                const size_t yi = tok * D_INNER + h * HEADDIM + col;
                const float2 yl = __half22float2(*(const __half2*)&y[yi]);
                const float2 xv = __half22float2(*(const __half2*)&conv[
                    base_conv + (size_t)t * CONV_DIM + h * HEADDIM + col]);
                const float2 zv = __half22float2(*(const __half2*)&zx[
                    base_z + (size_t)t * ZX16_W + h * HEADDIM + col]);
                const float v0 = (yl.x + acc[i][j][q * 2]     + Dp * xv.x) * fast_silu(zv.x);
                const float v1 = (yl.y + acc[i][j][q * 2 + 1] + Dp * xv.y) * fast_silu(zv.y);
                __half2 o; o.x = __float2half(v0); o.y = __float2half(v1);
                *(__half2*)&y[yi] = o;
            }
        }
    }
}

// ---------------------------------------------------------------------------
// Launch
// ---------------------------------------------------------------------------
extern "C" void kernel_launch(void* const* d_in, const int* in_sizes, int n_in,
                              void* d_out, int out_size)
{
    const float* hidden     = (const float*)d_in[0];
    const float* residual   = (const float*)d_in[1];
    const float* ssm_norm_w = (const float*)d_in[2];
    const float* mlp_norm_w = (const float*)d_in[3];
    const float* in_proj_w  = (const float*)d_in[4];
    const float* conv_w     = (const float*)d_in[5];
    const float* conv_b     = (const float*)d_in[6];
    const float* dt_bias    = (const float*)d_in[7];
    const float* A_log      = (const float*)d_in[8];
    const float* D_param    = (const float*)d_in[9];
    const float* out_proj_w = (const float*)d_in[10];
    const float* mlp_gate_w = (const float*)d_in[11];
    const float* mlp_up_w   = (const float*)d_in[12];
    const float* mlp_down_w = (const float*)d_in[13];

    float* out_h   = (float*)d_out;
    float* out_res = out_h + (size_t)ROWS * D_MODEL;

    void *p_res1, *p_h2, *p_dt;
    void *p_zx16, *p_cv16, *p_n, *p_y, *p_a;
    void *p_wi, *p_wo, *p_wm, *p_wd;
    cudaGetSymbolAddress(&p_res1, g_res1);
    cudaGetSymbolAddress(&p_h2,   g_h2);
    cudaGetSymbolAddress(&p_dt,   g_dt);
    cudaGetSymbolAddress(&p_zx16, g_zx16);
    cudaGetSymbolAddress(&p_cv16, g_cv16);
    cudaGetSymbolAddress(&p_n,    g_norm);
    cudaGetSymbolAddress(&p_y,    g_y);
    cudaGetSymbolAddress(&p_a,    g_act);
    cudaGetSymbolAddress(&p_wi,   g_wi);
    cudaGetSymbolAddress(&p_wo,   g_wo);
    cudaGetSymbolAddress(&p_wm,   g_wm);
    cudaGetSymbolAddress(&p_wd,   g_wd);

    cudaFuncSetAttribute(gemm_f16<0>,
                         cudaFuncAttributeMaxDynamicSharedMemorySize, GEMM_SMEM);
    cudaFuncSetAttribute(gemm_f16<1>,
                         cudaFuncAttributeMaxDynamicSharedMemorySize, GEMM_SMEM);
    cudaFuncSetAttribute(gemm_f16<2>,
                         cudaFuncAttributeMaxDynamicSharedMemorySize, GEMM_SMEM);
    cudaFuncSetAttribute(scan_correct_kernel,
                         cudaFuncAttributeMaxDynamicSharedMemorySize, CR_SMEM);

    // Weight conversions (fp16, padding / interleave)
    {
        size_t nr, nt;
        nr = (size_t)D_IN_PROJ * D_MODEL / 4; nt = (size_t)N_INPROJ_PAD * D_MODEL / 4;
        cvt_weight_kernel<<<(unsigned)((nt + 255) / 256), 256>>>(
            in_proj_w, (__half*)p_wi, nr, nt);
        nr = nt = (size_t)D_MODEL * D_INNER / 4;
        cvt_weight_kernel<<<(unsigned)((nt + 255) / 256), 256>>>(
            out_proj_w, (__half*)p_wo, nr, nt);
        nt = (size_t)MLP_2X * D_MODEL / 4;
        cvt_weight_pair_kernel<<<(unsigned)((nt + 255) / 256), 256>>>(
            mlp_gate_w, mlp_up_w, (__half*)p_wm);
        nr = nt = (size_t)D_MODEL * MLP_INNER / 4;
        cvt_weight_kernel<<<(unsigned)((nt + 255) / 256), 256>>>(
            mlp_down_w, (__half*)p_wd, nr, nt);
    }

    // 1) prenorm RMSNorm #1
    rmsnorm_prenorm_kernel<<<ROWS, 256>>>(hidden, residual, ssm_norm_w,
        (float*)p_res1, (__half*)p_n);
    // 2) in_proj -> fp16 z+xBC, fp32 dt
    gemm_f16<2><<<dim3(N_INPROJ_PAD / 256, ROWS / 128), 512, GEMM_SMEM>>>(
        (const __half*)p_n, (const __half*)p_wi,
        nullptr, (__half*)p_zx16, (float*)p_dt, ROWS, N_INPROJ_PAD, D_MODEL);
    // 3) causal depthwise conv + SiLU (fp16 in/out)
    conv_silu_kernel<<<(unsigned)(((size_t)ROWS * CONV_DIM + 255) / 256), 256>>>(
        (const __half*)p_zx16, conv_w, conv_b, (__half*)p_cv16);
    // 4) chunked selective scan: local scan + y_local, combine, mma correction
    scan_localy_kernel<<<dim3(NCHUNK, BATCH * NHEADS), 128>>>(
        (const __half*)p_cv16, (const float*)p_dt, dt_bias, A_log, (__half*)p_y);
    scan_combine_kernel<<<dim3(BATCH * NHEADS, 8), 256>>>();
    scan_correct_kernel<<<dim3(NCHUNK, BATCH * NHEADS), 128, CR_SMEM>>>(
        (const __half*)p_cv16, (const __half*)p_zx16, D_param, (__half*)p_y);
    // 5) out_proj
    gemm_f16<0><<<dim3(D_MODEL / 256, ROWS / 128), 512, GEMM_SMEM>>>(
        (const __half*)p_y, (const __half*)p_wo,
        (float*)p_h2, nullptr, nullptr, ROWS, D_MODEL, D_INNER);
    // 6) prenorm RMSNorm #2
    rmsnorm_prenorm_kernel<<<ROWS, 256>>>((const float*)p_h2, (const float*)p_res1,
        mlp_norm_w, out_res, (__half*)p_n);
    // 7) fused MLP gate+up GEMM with SwiGLU epilogue (interleaved weights)
    gemm_f16<1><<<dim3(MLP_2X / 256, ROWS / 128), 512, GEMM_SMEM>>>(
        (const __half*)p_n, (const __half*)p_wm,
        nullptr, (__half*)p_a, nullptr, ROWS, MLP_2X, D_MODEL);
    // 8) down projection -> first model output
    gemm_f16<0><<<dim3(D_MODEL / 256, ROWS / 128), 512, GEMM_SMEM>>>(
        (const __half*)p_a, (const __half*)p_wd,
        out_h, nullptr, nullptr, ROWS, D_MODEL, MLP_INNER);
}